// round 1
// baseline (speedup 1.0000x reference)
#include <cuda_runtime.h>
#include <math.h>

#define E_DIM 1024
#define QLEN  1024
#define BATCH 4
#define NH    16
#define DH    64
#define SQ    65   // smem row stride (floats) to dodge bank conflicts

// ---------------- scratch (device globals; no allocation allowed) ----------------
__device__ float g_q[BATCH * NH * QLEN * DH];     // [b][h][i][d]
__device__ float g_k[BATCH * NH * QLEN * DH];
__device__ float g_v[BATCH * NH * QLEN * DH];
__device__ float g_rp[NH * QLEN * DH];            // [h][t][d]
__device__ float g_ck[BATCH * NH * QLEN];         // rwb . k
__device__ float g_cr[NH * QLEN];                 // rrb . rp
__device__ float g_attn[BATCH * QLEN * E_DIM];    // attention out, token-major
__device__ float g_o[BATCH * QLEN * E_DIM];       // after Wo

// ---------------- generic 128x128 fp32 GEMM core (K=N=1024) ----------------
__device__ __forceinline__ void gemm_core(const float* __restrict__ A,
                                          const float* __restrict__ Bm,
                                          float (&acc)[8][8])
{
    __shared__ float As[16][132];
    __shared__ float Bs[16][132];
    const int tid = threadIdx.x;
    const int tx = tid & 15, ty = tid >> 4;
    const int m0 = blockIdx.y * 128, n0 = blockIdx.x * 128;

    for (int k0 = 0; k0 < E_DIM; k0 += 16) {
#pragma unroll
        for (int l = 0; l < 2; l++) {
            int t = tid * 2 + l;                       // 0..511
            int arow = t >> 2, ac4 = t & 3;
            float4 av = *(const float4*)(A + (size_t)(m0 + arow) * E_DIM + k0 + ac4 * 4);
            As[ac4 * 4 + 0][arow] = av.x;
            As[ac4 * 4 + 1][arow] = av.y;
            As[ac4 * 4 + 2][arow] = av.z;
            As[ac4 * 4 + 3][arow] = av.w;
            int brow = t >> 5, bc4 = t & 31;
            float4 bv = *(const float4*)(Bm + (size_t)(k0 + brow) * E_DIM + n0 + bc4 * 4);
            *(float4*)&Bs[brow][bc4 * 4] = bv;
        }
        __syncthreads();
#pragma unroll
        for (int k = 0; k < 16; k++) {
            float ar[8], br[8];
#pragma unroll
            for (int r = 0; r < 8; r++) ar[r] = As[k][ty + 16 * r];
#pragma unroll
            for (int c = 0; c < 8; c++) br[c] = Bs[k][tx + 16 * c];
#pragma unroll
            for (int r = 0; r < 8; r++)
#pragma unroll
                for (int c = 0; c < 8; c++)
                    acc[r][c] = fmaf(ar[r], br[c], acc[r][c]);
        }
        __syncthreads();
    }
}

// QKV projections: grid (8, 32, 3); z selects weight; head-major store
__global__ void __launch_bounds__(256) gemm_qkv(const float* __restrict__ A,
                                                const float* __restrict__ B0,
                                                const float* __restrict__ B1,
                                                const float* __restrict__ B2)
{
    const float* Bm = (blockIdx.z == 0) ? B0 : (blockIdx.z == 1) ? B1 : B2;
    float* C = (blockIdx.z == 0) ? g_q : (blockIdx.z == 1) ? g_k : g_v;
    float acc[8][8] = {};
    gemm_core(A, Bm, acc);
    const int tx = threadIdx.x & 15, ty = threadIdx.x >> 4;
    const int m0 = blockIdx.y * 128, n0 = blockIdx.x * 128;
#pragma unroll
    for (int r = 0; r < 8; r++) {
        int m = m0 + ty + 16 * r;
        int b = m >> 10, i = m & 1023;
#pragma unroll
        for (int c = 0; c < 8; c++) {
            int n = n0 + tx + 16 * c;
            int h = n >> 6, d = n & 63;
            C[(((size_t)b * NH + h) * QLEN + i) * DH + d] = acc[r][c];
        }
    }
}

// rp = r @ Wr: grid (8, 8, 1); head-major store (b==0)
__global__ void __launch_bounds__(256) gemm_rp(const float* __restrict__ A,
                                               const float* __restrict__ Bm)
{
    float acc[8][8] = {};
    gemm_core(A, Bm, acc);
    const int tx = threadIdx.x & 15, ty = threadIdx.x >> 4;
    const int m0 = blockIdx.y * 128, n0 = blockIdx.x * 128;
#pragma unroll
    for (int r = 0; r < 8; r++) {
        int m = m0 + ty + 16 * r;  // position t
#pragma unroll
        for (int c = 0; c < 8; c++) {
            int n = n0 + tx + 16 * c;
            int h = n >> 6, d = n & 63;
            g_rp[((size_t)h * QLEN + m) * DH + d] = acc[r][c];
        }
    }
}

// o = attn @ Wo: grid (8, 32, 1); plain row-major store
__global__ void __launch_bounds__(256) gemm_wo(const float* __restrict__ Bm)
{
    float acc[8][8] = {};
    gemm_core(g_attn, Bm, acc);
    const int tx = threadIdx.x & 15, ty = threadIdx.x >> 4;
    const int m0 = blockIdx.y * 128, n0 = blockIdx.x * 128;
#pragma unroll
    for (int r = 0; r < 8; r++)
#pragma unroll
        for (int c = 0; c < 8; c++)
            g_o[(size_t)(m0 + ty + 16 * r) * E_DIM + n0 + tx + 16 * c] = acc[r][c];
}

// ---------------- ck[b,h,j] = rwb[h].k ; cr[h,t] = rrb[h].rp ----------------
__global__ void __launch_bounds__(256) ckcr_kernel(const float* __restrict__ rwb,
                                                   const float* __restrict__ rrb)
{
    int gw = (blockIdx.x * blockDim.x + threadIdx.x) >> 5;
    int lane = threadIdx.x & 31;
    const int NCK = BATCH * NH * QLEN;  // 65536
    float s;
    if (gw < NCK) {
        int h = (gw >> 10) & (NH - 1);
        const float* row = g_k + (size_t)gw * DH;
        s = row[lane] * rwb[h * DH + lane] + row[lane + 32] * rwb[h * DH + lane + 32];
    } else {
        int w2 = gw - NCK;
        if (w2 >= NH * QLEN) return;
        int h = w2 >> 10;
        const float* row = g_rp + (size_t)w2 * DH;
        s = row[lane] * rrb[h * DH + lane] + row[lane + 32] * rrb[h * DH + lane + 32];
    }
#pragma unroll
    for (int off = 16; off; off >>= 1) s += __shfl_down_sync(0xffffffffu, s, off);
    if (lane == 0) {
        if (gw < NCK) g_ck[gw] = s;
        else g_cr[gw - NCK] = s;
    }
}

// ---------------- fused attention (flash-style, causal, rel-shift folded) ----------------
// grid (16 qtiles, 16 heads, 4 batch), 256 threads
// S[i,j] = ( q_i.(k_j + rp_t) + ck[j] + cr[t] ) / 32,  t = Q-1-(i-j)
__global__ void __launch_bounds__(256) attn_kernel()
{
    extern __shared__ float sm[];
    float* q_s  = sm;                 // 64*SQ
    float* k_s  = q_s + 64 * SQ;
    float* v_s  = k_s + 64 * SQ;
    float* rp_s = v_s + 64 * SQ;      // 128*SQ
    float* S_s  = rp_s + 128 * SQ;    // 64*SQ
    float* ck_s = S_s + 64 * SQ;      // 64
    float* cr_s = ck_s + 64;          // 128
    float* m_s  = cr_s + 128;         // 64
    float* l_s  = m_s + 64;           // 64
    float* c_s  = l_s + 64;           // 64

    const int tid = threadIdx.x;
    const int tx = tid & 15, ty = tid >> 4;
    const int qt = 15 - blockIdx.x;   // heavy tiles scheduled first
    const int h  = blockIdx.y;
    const int b  = blockIdx.z;
    const int i0 = qt * 64;
    const size_t headbase = ((size_t)b * NH + h) * QLEN * DH;
    const size_t rpbase = (size_t)h * QLEN * DH;

    // load q tile
#pragma unroll
    for (int l = 0; l < 16; l++) {
        int idx = tid + 256 * l;
        int row = idx >> 6, d = idx & 63;
        q_s[row * SQ + d] = g_q[headbase + (size_t)(i0 + row) * DH + d];
    }
    if (tid < 64) { m_s[tid] = -INFINITY; l_s[tid] = 0.f; }
    float acc_o[4][4] = {};
    const int t00 = 15 - ty + tx;     // rp window row base for this thread
    __syncthreads();

    for (int kt = 0; kt <= qt; kt++) {
        const int j0 = kt * 64;
        const int m_base = 960 - i0 + j0;   // >= 0 always
        // load k, v tiles
#pragma unroll
        for (int l = 0; l < 16; l++) {
            int idx = tid + 256 * l;
            int row = idx >> 6, d = idx & 63;
            k_s[row * SQ + d] = g_k[headbase + (size_t)(j0 + row) * DH + d];
            v_s[row * SQ + d] = g_v[headbase + (size_t)(j0 + row) * DH + d];
        }
        // load rp 128-row window (clamped; out-of-range rows are masked anyway)
#pragma unroll
        for (int l = 0; l < 32; l++) {
            int idx = tid + 256 * l;
            int row = idx >> 6, d = idx & 63;
            int mg = m_base + row;
            rp_s[row * SQ + d] = (mg < QLEN) ? g_rp[rpbase + (size_t)mg * DH + d] : 0.f;
        }
        if (tid < 64) {
            ck_s[tid] = g_ck[((size_t)b * NH + h) * QLEN + j0 + tid];
        } else if (tid < 192) {
            int t = tid - 64;
            int mg = m_base + t;
            cr_s[t] = (mg < QLEN) ? g_cr[h * QLEN + mg] : 0.f;
        }
        __syncthreads();

        // S tile: strided 4x4 per thread (rows ty+16r, cols tx+16c)
        float acc_s[4][4] = {};
#pragma unroll
        for (int d = 0; d < 64; d++) {
            float ar[4], kr[4], rt[7];
#pragma unroll
            for (int r = 0; r < 4; r++) ar[r] = q_s[(ty + 16 * r) * SQ + d];
#pragma unroll
            for (int c = 0; c < 4; c++) kr[c] = k_s[(tx + 16 * c) * SQ + d];
#pragma unroll
            for (int u = 0; u < 7; u++) rt[u] = rp_s[(t00 + 16 * u) * SQ + d];
#pragma unroll
            for (int r = 0; r < 4; r++)
#pragma unroll
                for (int c = 0; c < 4; c++)
                    acc_s[r][c] += ar[r] * (kr[c] + rt[c - r + 3]);
        }
#pragma unroll
        for (int r = 0; r < 4; r++) {
            int il = ty + 16 * r;
#pragma unroll
            for (int c = 0; c < 4; c++) {
                int jl = tx + 16 * c;
                int u = c - r + 3;
                float val = (acc_s[r][c] + ck_s[jl] + cr_s[t00 + 16 * u]) * 0.03125f;
                if (kt == qt && jl > il) val = -1e30f;
                S_s[il * SQ + jl] = val;
            }
        }
        __syncthreads();

        // online softmax row update (64 row-threads)
        if (tid < 64) {
            int row = tid;
            float mo = m_s[row];
            float mx = mo;
            for (int j = 0; j < 64; j++) mx = fmaxf(mx, S_s[row * SQ + j]);
            float corr = __expf(mo - mx);
            float sum = 0.f;
            for (int j = 0; j < 64; j++) {
                float p = __expf(S_s[row * SQ + j] - mx);
                S_s[row * SQ + j] = p;
                sum += p;
            }
            l_s[row] = l_s[row] * corr + sum;
            m_s[row] = mx;
            c_s[row] = corr;
        }
        __syncthreads();

        // PV accumulate
        float cf[4];
#pragma unroll
        for (int r = 0; r < 4; r++) cf[r] = c_s[ty + 16 * r];
#pragma unroll
        for (int r = 0; r < 4; r++)
#pragma unroll
            for (int c = 0; c < 4; c++) acc_o[r][c] *= cf[r];
        for (int jl = 0; jl < 64; jl++) {
            float pr[4], vr[4];
#pragma unroll
            for (int r = 0; r < 4; r++) pr[r] = S_s[(ty + 16 * r) * SQ + jl];
#pragma unroll
            for (int c = 0; c < 4; c++) vr[c] = v_s[jl * SQ + tx + 16 * c];
#pragma unroll
            for (int r = 0; r < 4; r++)
#pragma unroll
                for (int c = 0; c < 4; c++)
                    acc_o[r][c] = fmaf(pr[r], vr[c], acc_o[r][c]);
        }
        __syncthreads();
    }

    // write out, token-major for the Wo GEMM
#pragma unroll
    for (int r = 0; r < 4; r++) {
        int i = i0 + ty + 16 * r;
        float invl = 1.f / l_s[ty + 16 * r];
#pragma unroll
        for (int c = 0; c < 4; c++) {
            int d = tx + 16 * c;
            g_attn[((size_t)b * QLEN + i) * E_DIM + h * DH + d] = acc_o[r][c] * invl;
        }
    }
}

// ---------------- residual + layernorm ----------------
__global__ void __launch_bounds__(256) addln_kernel(const float* __restrict__ w,
                                                    const float* __restrict__ gamma,
                                                    const float* __restrict__ beta,
                                                    float* __restrict__ out)
{
    __shared__ float xs[E_DIM];
    __shared__ float red[64];
    int row = blockIdx.x;
    size_t base = (size_t)row * E_DIM;
    float s = 0.f, s2 = 0.f;
    for (int j = threadIdx.x; j < E_DIM; j += 256) {
        float x = w[base + j] + g_o[base + j];
        xs[j] = x;
        s += x; s2 += x * x;
    }
#pragma unroll
    for (int off = 16; off; off >>= 1) {
        s  += __shfl_down_sync(0xffffffffu, s, off);
        s2 += __shfl_down_sync(0xffffffffu, s2, off);
    }
    int wid = threadIdx.x >> 5, lane = threadIdx.x & 31;
    if (lane == 0) { red[wid] = s; red[32 + wid] = s2; }
    __syncthreads();
    if (threadIdx.x == 0) {
        float S = 0.f, S2 = 0.f;
        for (int i = 0; i < 8; i++) { S += red[i]; S2 += red[32 + i]; }
        red[0] = S; red[1] = S2;
    }
    __syncthreads();
    float mean = red[0] * (1.f / E_DIM);
    float var = red[1] * (1.f / E_DIM) - mean * mean;
    float inv = rsqrtf(var + 1e-3f);
    for (int j = threadIdx.x; j < E_DIM; j += 256)
        out[base + j] = (xs[j] - mean) * inv * gamma[j] + beta[j];
}

// ---------------- launch ----------------
extern "C" void kernel_launch(void* const* d_in, const int* in_sizes, int n_in,
                              void* d_out, int out_size)
{
    const float* w     = (const float*)d_in[0];
    const float* r     = (const float*)d_in[1];
    const float* rwb   = (const float*)d_in[2];
    const float* rrb   = (const float*)d_in[3];
    // d_in[4] attn_mask: strictly-causal, computed analytically
    const float* Wq    = (const float*)d_in[5];
    const float* Wk    = (const float*)d_in[6];
    const float* Wv    = (const float*)d_in[7];
    const float* Wr    = (const float*)d_in[8];
    const float* Wo    = (const float*)d_in[9];
    const float* gamma = (const float*)d_in[10];
    const float* beta  = (const float*)d_in[11];
    float* out = (float*)d_out;

    const int ATTN_SMEM = (64 * SQ * 4 + 128 * SQ + 64 + 128 + 64 * 3) * (int)sizeof(float);
    cudaFuncSetAttribute(attn_kernel, cudaFuncAttributeMaxDynamicSharedMemorySize, ATTN_SMEM);

    gemm_qkv<<<dim3(8, 32, 3), 256>>>(w, Wq, Wk, Wv);
    gemm_rp<<<dim3(8, 8, 1), 256>>>(r, Wr);
    ckcr_kernel<<<10240, 256>>>(rwb, rrb);
    attn_kernel<<<dim3(16, 16, 4), 256, ATTN_SMEM>>>();
    gemm_wo<<<dim3(8, 32, 1), 256>>>(Wo);
    addln_kernel<<<4096, 256>>>(w, gamma, beta, out);
}

// round 3
// speedup vs baseline: 1.4973x; 1.4973x over previous
#include <cuda_runtime.h>
#include <math.h>
#include <stdint.h>

#define E_DIM 1024
#define QLEN  1024
#define BATCH 4
#define NH    16
#define DH    64
#define SQ    65   // smem row stride (floats) to dodge bank conflicts

// ---------------- scratch (device globals; no allocation allowed) ----------------
__device__ float g_q[BATCH * NH * QLEN * DH];     // [b][h][i][d]
__device__ float g_k[BATCH * NH * QLEN * DH];
__device__ float g_v[BATCH * NH * QLEN * DH];
__device__ float g_rp[NH * QLEN * DH];            // [h][t][d]
__device__ float g_ck[BATCH * NH * QLEN];         // rwb . k
__device__ float g_cr[NH * QLEN];                 // rrb . rp
__device__ float g_attn[BATCH * QLEN * E_DIM];    // attention out, token-major
__device__ float g_o[BATCH * QLEN * E_DIM];       // after Wo
__device__ float g_wt[5 * E_DIM * E_DIM];         // transposed tf32-rounded weights

// ================= helpers =================
__device__ __forceinline__ float tf32r(float x) {
    asm("cvt.rna.tf32.f32 %0, %1;" : "=f"(x) : "f"(x));
    return x;
}
__device__ __forceinline__ uint32_t tf32u(float x) {
    uint32_t u;
    asm("cvt.rna.tf32.f32 %0, %1;" : "=r"(u) : "f"(x));
    return u;
}

// ---------------- weight transpose + tf32 round: 5 x 1024x1024 ----------------
__global__ void __launch_bounds__(256) transpose5(const float* __restrict__ a0,
                                                  const float* __restrict__ a1,
                                                  const float* __restrict__ a2,
                                                  const float* __restrict__ a3,
                                                  const float* __restrict__ a4)
{
    __shared__ float t[32][33];
    const float* src = (blockIdx.z == 0) ? a0 : (blockIdx.z == 1) ? a1 :
                       (blockIdx.z == 2) ? a2 : (blockIdx.z == 3) ? a3 : a4;
    float* dst = g_wt + (size_t)blockIdx.z * E_DIM * E_DIM;
    int x = blockIdx.x * 32 + threadIdx.x;
    int y0 = blockIdx.y * 32 + threadIdx.y;
#pragma unroll
    for (int j = 0; j < 4; j++)
        t[threadIdx.y + 8 * j][threadIdx.x] = src[(size_t)(y0 + 8 * j) * E_DIM + x];
    __syncthreads();
    int x2 = blockIdx.y * 32 + threadIdx.x;
    int y2 = blockIdx.x * 32 + threadIdx.y;
#pragma unroll
    for (int j = 0; j < 4; j++)
        dst[(size_t)(y2 + 8 * j) * E_DIM + x2] = tf32r(t[threadIdx.x][threadIdx.y + 8 * j]);
}

// ---------------- mma.sync tf32 GEMM: C[MxN] = A[MxK] * Bt[NxK]^T, K=1024 ----------------
// 256 threads = 8 warps (2 m-rows x 4 n-cols), block tile 128x128, k-chunk 16.
// smem holds tiles in exact fragment order -> conflict-free v4/v2 loads in hot loop.
// mode 0: head-major scatter with batch (QKV), 1: head-major no batch (rp), 2: row-major
__global__ void __launch_bounds__(256, 2) gemm_mma(const float* __restrict__ A,
                                                   const float* __restrict__ Bt,
                                                   float* __restrict__ C,
                                                   int mode)
{
    __shared__ uint32_t sA[2][2048];  // [buf][atomM(8)][ks(2)][lane(32)][reg(4)]
    __shared__ uint32_t sB[2][2048];  // [buf][atomN(16)][ks(2)][lane(32)][reg(2)]

    const int tid = threadIdx.x;
    const int wid = tid >> 5, lane = tid & 31;
    const int mw = wid >> 2, nw = wid & 3;
    const int g = lane >> 2, tt = lane & 3;
    const int m0 = blockIdx.y * 128, n0 = blockIdx.x * 128;

    // precomputed scatter offsets (word indices), invariant across k-chunks
    uint32_t a_off[8], b_off[8];
#pragma unroll
    for (int l = 0; l < 2; l++) {
        int t = tid * 2 + l;
        int row = t >> 2, q4 = t & 3;
#pragma unroll
        for (int e = 0; e < 4; e++) {
            int k = q4 * 4 + e;
            int ks = k >> 3, kk = k & 7, ktt = kk & 3, kh = kk >> 2;
            int matom = row >> 4;           // global m-atom 0..7
            int gi = row & 7, hi = (row >> 3) & 1;
            a_off[l * 4 + e] = (uint32_t)((((matom * 2 + ks) * 32 + gi * 4 + ktt) << 2) + hi + 2 * kh);
            int natom = row >> 3;           // global n-atom 0..15
            int gb = row & 7;
            b_off[l * 4 + e] = (uint32_t)((((natom * 2 + ks) * 32 + gb * 4 + ktt) << 1) + kh);
        }
    }
    const int arow0 = (tid * 2) >> 2, aq0 = (tid * 2) & 3;
    const int arow1 = (tid * 2 + 1) >> 2, aq1 = (tid * 2 + 1) & 3;
    const float* Ap = A + (size_t)m0 * E_DIM;
    const float* Bp = Bt + (size_t)n0 * E_DIM;

    float d[4][4][4];
#pragma unroll
    for (int i = 0; i < 4; i++)
#pragma unroll
        for (int j = 0; j < 4; j++)
#pragma unroll
            for (int e = 0; e < 4; e++) d[i][j][e] = 0.f;

    float4 ra0, ra1, rb0, rb1;

#define LOADC(c) do { \
    ra0 = *(const float4*)(Ap + (size_t)arow0 * E_DIM + (c) * 16 + aq0 * 4); \
    ra1 = *(const float4*)(Ap + (size_t)arow1 * E_DIM + (c) * 16 + aq1 * 4); \
    rb0 = *(const float4*)(Bp + (size_t)arow0 * E_DIM + (c) * 16 + aq0 * 4); \
    rb1 = *(const float4*)(Bp + (size_t)arow1 * E_DIM + (c) * 16 + aq1 * 4); \
} while (0)

#define SCAT(bf_) do { \
    uint32_t* a_s = sA[bf_]; uint32_t* b_s = sB[bf_]; \
    a_s[a_off[0]] = tf32u(ra0.x); a_s[a_off[1]] = tf32u(ra0.y); \
    a_s[a_off[2]] = tf32u(ra0.z); a_s[a_off[3]] = tf32u(ra0.w); \
    a_s[a_off[4]] = tf32u(ra1.x); a_s[a_off[5]] = tf32u(ra1.y); \
    a_s[a_off[6]] = tf32u(ra1.z); a_s[a_off[7]] = tf32u(ra1.w); \
    b_s[b_off[0]] = __float_as_uint(rb0.x); b_s[b_off[1]] = __float_as_uint(rb0.y); \
    b_s[b_off[2]] = __float_as_uint(rb0.z); b_s[b_off[3]] = __float_as_uint(rb0.w); \
    b_s[b_off[4]] = __float_as_uint(rb1.x); b_s[b_off[5]] = __float_as_uint(rb1.y); \
    b_s[b_off[6]] = __float_as_uint(rb1.z); b_s[b_off[7]] = __float_as_uint(rb1.w); \
} while (0)

    LOADC(0);
    SCAT(0);
    __syncthreads();

    for (int c = 0; c < 64; c++) {
        const int buf = c & 1;
        if (c < 63) LOADC(c + 1);
#pragma unroll
        for (int ks = 0; ks < 2; ks++) {
            uint4 af[4];
            uint2 bfr[4];
#pragma unroll
            for (int ma = 0; ma < 4; ma++)
                af[ma] = *(const uint4*)&sA[buf][(((mw * 4 + ma) * 2 + ks) * 32 + lane) << 2];
#pragma unroll
            for (int nb = 0; nb < 4; nb++)
                bfr[nb] = *(const uint2*)&sB[buf][(((nw * 4 + nb) * 2 + ks) * 32 + lane) << 1];
#pragma unroll
            for (int ma = 0; ma < 4; ma++)
#pragma unroll
                for (int nb = 0; nb < 4; nb++)
                    asm volatile(
                        "mma.sync.aligned.m16n8k8.row.col.f32.tf32.tf32.f32 "
                        "{%0,%1,%2,%3}, {%4,%5,%6,%7}, {%8,%9}, {%0,%1,%2,%3};"
                        : "+f"(d[ma][nb][0]), "+f"(d[ma][nb][1]),
                          "+f"(d[ma][nb][2]), "+f"(d[ma][nb][3])
                        : "r"(af[ma].x), "r"(af[ma].y), "r"(af[ma].z), "r"(af[ma].w),
                          "r"(bfr[nb].x), "r"(bfr[nb].y));
        }
        if (c < 63) SCAT(buf ^ 1);
        __syncthreads();
    }
#undef LOADC
#undef SCAT

    // epilogue: direct register -> gmem stores (float2 pairs)
#pragma unroll
    for (int ma = 0; ma < 4; ma++) {
        const int m_lo = m0 + mw * 64 + ma * 16 + g;
#pragma unroll
        for (int nb = 0; nb < 4; nb++) {
            const int n = n0 + nw * 32 + nb * 8 + tt * 2;
#pragma unroll
            for (int half = 0; half < 2; half++) {
                const int m = m_lo + half * 8;
                float2 v = make_float2(d[ma][nb][half * 2], d[ma][nb][half * 2 + 1]);
                if (mode == 0) {
                    int b = m >> 10, i = m & 1023, h = n >> 6, dd = n & 63;
                    *(float2*)&C[(((size_t)b * NH + h) * QLEN + i) * DH + dd] = v;
                } else if (mode == 1) {
                    int h = n >> 6, dd = n & 63;
                    *(float2*)&C[((size_t)h * QLEN + m) * DH + dd] = v;
                } else {
                    *(float2*)&C[(size_t)m * E_DIM + n] = v;
                }
            }
        }
    }
}

// ---------------- ck[b,h,j] = rwb[h].k ; cr[h,t] = rrb[h].rp ----------------
__global__ void __launch_bounds__(256) ckcr_kernel(const float* __restrict__ rwb,
                                                   const float* __restrict__ rrb)
{
    int gw = (blockIdx.x * blockDim.x + threadIdx.x) >> 5;
    int lane = threadIdx.x & 31;
    const int NCK = BATCH * NH * QLEN;  // 65536
    float s;
    if (gw < NCK) {
        int h = (gw >> 10) & (NH - 1);
        const float* row = g_k + (size_t)gw * DH;
        s = row[lane] * rwb[h * DH + lane] + row[lane + 32] * rwb[h * DH + lane + 32];
    } else {
        int w2 = gw - NCK;
        if (w2 >= NH * QLEN) return;
        int h = w2 >> 10;
        const float* row = g_rp + (size_t)w2 * DH;
        s = row[lane] * rrb[h * DH + lane] + row[lane + 32] * rrb[h * DH + lane + 32];
    }
#pragma unroll
    for (int off = 16; off; off >>= 1) s += __shfl_down_sync(0xffffffffu, s, off);
    if (lane == 0) {
        if (gw < NCK) g_ck[gw] = s;
        else g_cr[gw - NCK] = s;
    }
}

// ---------------- fused attention (flash-style, causal, rel-shift folded) ----------------
// grid (16 qtiles, 16 heads, 4 batch), 256 threads
// S[i,j] = ( q_i.(k_j + rp_t) + ck[j] + cr[t] ) / 32,  t = Q-1-(i-j)
__global__ void __launch_bounds__(256) attn_kernel()
{
    extern __shared__ float sm[];
    float* q_s  = sm;                 // 64*SQ
    float* k_s  = q_s + 64 * SQ;
    float* v_s  = k_s + 64 * SQ;
    float* rp_s = v_s + 64 * SQ;      // 128*SQ
    float* S_s  = rp_s + 128 * SQ;    // 64*SQ
    float* ck_s = S_s + 64 * SQ;      // 64
    float* cr_s = ck_s + 64;          // 128
    float* m_s  = cr_s + 128;         // 64
    float* l_s  = m_s + 64;           // 64
    float* c_s  = l_s + 64;           // 64

    const int tid = threadIdx.x;
    const int tx = tid & 15, ty = tid >> 4;
    const int qt = 15 - blockIdx.x;   // heavy tiles scheduled first
    const int h  = blockIdx.y;
    const int b  = blockIdx.z;
    const int i0 = qt * 64;
    const size_t headbase = ((size_t)b * NH + h) * QLEN * DH;
    const size_t rpbase = (size_t)h * QLEN * DH;

    // load q tile
#pragma unroll
    for (int l = 0; l < 16; l++) {
        int idx = tid + 256 * l;
        int row = idx >> 6, d = idx & 63;
        q_s[row * SQ + d] = g_q[headbase + (size_t)(i0 + row) * DH + d];
    }
    if (tid < 64) { m_s[tid] = -INFINITY; l_s[tid] = 0.f; }
    float acc_o[4][4] = {};
    const int t00 = 15 - ty + tx;     // rp window row base for this thread
    __syncthreads();

    for (int kt = 0; kt <= qt; kt++) {
        const int j0 = kt * 64;
        const int m_base = 960 - i0 + j0;   // >= 0 always
        // load k, v tiles
#pragma unroll
        for (int l = 0; l < 16; l++) {
            int idx = tid + 256 * l;
            int row = idx >> 6, d = idx & 63;
            k_s[row * SQ + d] = g_k[headbase + (size_t)(j0 + row) * DH + d];
            v_s[row * SQ + d] = g_v[headbase + (size_t)(j0 + row) * DH + d];
        }
        // load rp 128-row window (clamped; out-of-range rows are masked anyway)
#pragma unroll
        for (int l = 0; l < 32; l++) {
            int idx = tid + 256 * l;
            int row = idx >> 6, d = idx & 63;
            int mg = m_base + row;
            rp_s[row * SQ + d] = (mg < QLEN) ? g_rp[rpbase + (size_t)mg * DH + d] : 0.f;
        }
        if (tid < 64) {
            ck_s[tid] = g_ck[((size_t)b * NH + h) * QLEN + j0 + tid];
        } else if (tid < 192) {
            int t = tid - 64;
            int mg = m_base + t;
            cr_s[t] = (mg < QLEN) ? g_cr[h * QLEN + mg] : 0.f;
        }
        __syncthreads();

        // S tile: strided 4x4 per thread (rows ty+16r, cols tx+16c)
        float acc_s[4][4] = {};
#pragma unroll
        for (int d = 0; d < 64; d++) {
            float ar[4], kr[4], rt[7];
#pragma unroll
            for (int r = 0; r < 4; r++) ar[r] = q_s[(ty + 16 * r) * SQ + d];
#pragma unroll
            for (int c = 0; c < 4; c++) kr[c] = k_s[(tx + 16 * c) * SQ + d];
#pragma unroll
            for (int u = 0; u < 7; u++) rt[u] = rp_s[(t00 + 16 * u) * SQ + d];
#pragma unroll
            for (int r = 0; r < 4; r++)
#pragma unroll
                for (int c = 0; c < 4; c++)
                    acc_s[r][c] += ar[r] * (kr[c] + rt[c - r + 3]);
        }
#pragma unroll
        for (int r = 0; r < 4; r++) {
            int il = ty + 16 * r;
#pragma unroll
            for (int c = 0; c < 4; c++) {
                int jl = tx + 16 * c;
                int u = c - r + 3;
                float val = (acc_s[r][c] + ck_s[jl] + cr_s[t00 + 16 * u]) * 0.03125f;
                if (kt == qt && jl > il) val = -1e30f;
                S_s[il * SQ + jl] = val;
            }
        }
        __syncthreads();

        // online softmax row update (64 row-threads)
        if (tid < 64) {
            int row = tid;
            float mo = m_s[row];
            float mx = mo;
            for (int j = 0; j < 64; j++) mx = fmaxf(mx, S_s[row * SQ + j]);
            float corr = __expf(mo - mx);
            float sum = 0.f;
            for (int j = 0; j < 64; j++) {
                float p = __expf(S_s[row * SQ + j] - mx);
                S_s[row * SQ + j] = p;
                sum += p;
            }
            l_s[row] = l_s[row] * corr + sum;
            m_s[row] = mx;
            c_s[row] = corr;
        }
        __syncthreads();

        // PV accumulate
        float cf[4];
#pragma unroll
        for (int r = 0; r < 4; r++) cf[r] = c_s[ty + 16 * r];
#pragma unroll
        for (int r = 0; r < 4; r++)
#pragma unroll
            for (int c = 0; c < 4; c++) acc_o[r][c] *= cf[r];
        for (int jl = 0; jl < 64; jl++) {
            float pr[4], vr[4];
#pragma unroll
            for (int r = 0; r < 4; r++) pr[r] = S_s[(ty + 16 * r) * SQ + jl];
#pragma unroll
            for (int c = 0; c < 4; c++) vr[c] = v_s[jl * SQ + tx + 16 * c];
#pragma unroll
            for (int r = 0; r < 4; r++)
#pragma unroll
                for (int c = 0; c < 4; c++)
                    acc_o[r][c] = fmaf(pr[r], vr[c], acc_o[r][c]);
        }
        __syncthreads();
    }

    // write out, token-major for the Wo GEMM
#pragma unroll
    for (int r = 0; r < 4; r++) {
        int i = i0 + ty + 16 * r;
        float invl = 1.f / l_s[ty + 16 * r];
#pragma unroll
        for (int c = 0; c < 4; c++) {
            int d = tx + 16 * c;
            g_attn[((size_t)b * QLEN + i) * E_DIM + h * DH + d] = acc_o[r][c] * invl;
        }
    }
}

// ---------------- residual + layernorm ----------------
__global__ void __launch_bounds__(256) addln_kernel(const float* __restrict__ w,
                                                    const float* __restrict__ gamma,
                                                    const float* __restrict__ beta,
                                                    float* __restrict__ out)
{
    __shared__ float xs[E_DIM];
    __shared__ float red[64];
    int row = blockIdx.x;
    size_t base = (size_t)row * E_DIM;
    float s = 0.f, s2 = 0.f;
    for (int j = threadIdx.x; j < E_DIM; j += 256) {
        float x = w[base + j] + g_o[base + j];
        xs[j] = x;
        s += x; s2 += x * x;
    }
#pragma unroll
    for (int off = 16; off; off >>= 1) {
        s  += __shfl_down_sync(0xffffffffu, s, off);
        s2 += __shfl_down_sync(0xffffffffu, s2, off);
    }
    int wid = threadIdx.x >> 5, lane = threadIdx.x & 31;
    if (lane == 0) { red[wid] = s; red[32 + wid] = s2; }
    __syncthreads();
    if (threadIdx.x == 0) {
        float S = 0.f, S2 = 0.f;
        for (int i = 0; i < 8; i++) { S += red[i]; S2 += red[32 + i]; }
        red[0] = S; red[1] = S2;
    }
    __syncthreads();
    float mean = red[0] * (1.f / E_DIM);
    float var = red[1] * (1.f / E_DIM) - mean * mean;
    float inv = rsqrtf(var + 1e-3f);
    for (int j = threadIdx.x; j < E_DIM; j += 256)
        out[base + j] = (xs[j] - mean) * inv * gamma[j] + beta[j];
}

// ---------------- launch ----------------
extern "C" void kernel_launch(void* const* d_in, const int* in_sizes, int n_in,
                              void* d_out, int out_size)
{
    const float* w     = (const float*)d_in[0];
    const float* r     = (const float*)d_in[1];
    const float* rwb   = (const float*)d_in[2];
    const float* rrb   = (const float*)d_in[3];
    // d_in[4] attn_mask: strictly-causal, computed analytically
    const float* Wq    = (const float*)d_in[5];
    const float* Wk    = (const float*)d_in[6];
    const float* Wv    = (const float*)d_in[7];
    const float* Wr    = (const float*)d_in[8];
    const float* Wo    = (const float*)d_in[9];
    const float* gamma = (const float*)d_in[10];
    const float* beta  = (const float*)d_in[11];
    float* out = (float*)d_out;

    const int ATTN_SMEM = (64 * SQ * 4 + 128 * SQ + 64 + 128 + 64 * 3) * (int)sizeof(float);
    cudaFuncSetAttribute(attn_kernel, cudaFuncAttributeMaxDynamicSharedMemorySize, ATTN_SMEM);

    // device pointers to scratch symbols (host-side, cheap, capture-safe)
    static float* p_wt = nullptr;
    static float* p_q = nullptr; static float* p_k = nullptr; static float* p_v = nullptr;
    static float* p_rp = nullptr; static float* p_attn = nullptr; static float* p_o = nullptr;
    if (!p_wt) {
        cudaGetSymbolAddress((void**)&p_wt, g_wt);
        cudaGetSymbolAddress((void**)&p_q, g_q);
        cudaGetSymbolAddress((void**)&p_k, g_k);
        cudaGetSymbolAddress((void**)&p_v, g_v);
        cudaGetSymbolAddress((void**)&p_rp, g_rp);
        cudaGetSymbolAddress((void**)&p_attn, g_attn);
        cudaGetSymbolAddress((void**)&p_o, g_o);
    }
    const size_t WSZ = (size_t)E_DIM * E_DIM;

    transpose5<<<dim3(32, 32, 5), dim3(32, 8)>>>(Wq, Wk, Wv, Wr, Wo);
    gemm_mma<<<dim3(8, 32), 256>>>(w, p_wt + 0 * WSZ, p_q, 0);
    gemm_mma<<<dim3(8, 32), 256>>>(w, p_wt + 1 * WSZ, p_k, 0);
    gemm_mma<<<dim3(8, 32), 256>>>(w, p_wt + 2 * WSZ, p_v, 0);
    gemm_mma<<<dim3(8, 8),  256>>>(r, p_wt + 3 * WSZ, p_rp, 1);
    ckcr_kernel<<<10240, 256>>>(rwb, rrb);
    attn_kernel<<<dim3(16, 16, 4), 256, ATTN_SMEM>>>();
    gemm_mma<<<dim3(8, 32), 256>>>(p_attn, p_wt + 4 * WSZ, p_o, 2);
    addln_kernel<<<4096, 256>>>(w, gamma, beta, out);
}

// round 4
// speedup vs baseline: 1.9984x; 1.3346x over previous
#include <cuda_runtime.h>
#include <math.h>
#include <stdint.h>

#define E_DIM 1024
#define QLEN  1024
#define BATCH 4
#define NH    16
#define DH    64
#define SQ    65   // gemm smem pad (unused by attn)

// attention smem strides
#define SA 68   // q2/k/rp stride (64 data + 4 aux cols; bank = 4g+tt, conflict-free)
#define SV 72   // v stride (bank = 8tt+g, conflict-free)
#define SS 68   // S stride

// ---------------- scratch (device globals; no allocation allowed) ----------------
__device__ float g_q[BATCH * NH * QLEN * DH];     // [b][h][i][d]
__device__ float g_k[BATCH * NH * QLEN * DH];
__device__ float g_v[BATCH * NH * QLEN * DH];
__device__ float g_rp[NH * QLEN * DH];            // [h][t][d]
__device__ float g_ck[BATCH * NH * QLEN];         // rwb . k
__device__ float g_cr[NH * QLEN];                 // rrb . rp
__device__ float g_attn[BATCH * QLEN * E_DIM];    // attention out, token-major
__device__ float g_o[BATCH * QLEN * E_DIM];       // after Wo
__device__ float g_wt[5 * E_DIM * E_DIM];         // transposed tf32-rounded weights

// ================= helpers =================
__device__ __forceinline__ float tf32r(float x) {
    asm("cvt.rna.tf32.f32 %0, %1;" : "=f"(x) : "f"(x));
    return x;
}
__device__ __forceinline__ uint32_t tf32u(float x) {
    uint32_t u;
    asm("cvt.rna.tf32.f32 %0, %1;" : "=r"(u) : "f"(x));
    return u;
}

#define MMA8(d, a0, a1, a2, a3, b0, b1) \
    asm volatile("mma.sync.aligned.m16n8k8.row.col.f32.tf32.tf32.f32 " \
        "{%0,%1,%2,%3}, {%4,%5,%6,%7}, {%8,%9}, {%0,%1,%2,%3};" \
        : "+f"((d)[0]), "+f"((d)[1]), "+f"((d)[2]), "+f"((d)[3]) \
        : "r"(a0), "r"(a1), "r"(a2), "r"(a3), "r"(b0), "r"(b1))

#define MMA4(d, a0, a1, b0) \
    asm volatile("mma.sync.aligned.m16n8k4.row.col.f32.tf32.tf32.f32 " \
        "{%0,%1,%2,%3}, {%4,%5}, {%6}, {%0,%1,%2,%3};" \
        : "+f"((d)[0]), "+f"((d)[1]), "+f"((d)[2]), "+f"((d)[3]) \
        : "r"(a0), "r"(a1), "r"(b0))

// ---------------- weight transpose + tf32 round: 5 x 1024x1024 ----------------
__global__ void __launch_bounds__(256) transpose5(const float* __restrict__ a0,
                                                  const float* __restrict__ a1,
                                                  const float* __restrict__ a2,
                                                  const float* __restrict__ a3,
                                                  const float* __restrict__ a4)
{
    __shared__ float t[32][33];
    const float* src = (blockIdx.z == 0) ? a0 : (blockIdx.z == 1) ? a1 :
                       (blockIdx.z == 2) ? a2 : (blockIdx.z == 3) ? a3 : a4;
    float* dst = g_wt + (size_t)blockIdx.z * E_DIM * E_DIM;
    int x = blockIdx.x * 32 + threadIdx.x;
    int y0 = blockIdx.y * 32 + threadIdx.y;
#pragma unroll
    for (int j = 0; j < 4; j++)
        t[threadIdx.y + 8 * j][threadIdx.x] = src[(size_t)(y0 + 8 * j) * E_DIM + x];
    __syncthreads();
    int x2 = blockIdx.y * 32 + threadIdx.x;
    int y2 = blockIdx.x * 32 + threadIdx.y;
#pragma unroll
    for (int j = 0; j < 4; j++)
        dst[(size_t)(y2 + 8 * j) * E_DIM + x2] = tf32r(t[threadIdx.x][threadIdx.y + 8 * j]);
}

// ---------------- mma.sync tf32 GEMM: C[MxN] = A[MxK] * Bt[NxK]^T, K=1024 ----------------
__global__ void __launch_bounds__(256, 2) gemm_mma(const float* __restrict__ A,
                                                   const float* __restrict__ Bt,
                                                   float* __restrict__ C,
                                                   int mode)
{
    __shared__ uint32_t sA[2][2048];
    __shared__ uint32_t sB[2][2048];

    const int tid = threadIdx.x;
    const int wid = tid >> 5, lane = tid & 31;
    const int mw = wid >> 2, nw = wid & 3;
    const int g = lane >> 2, tt = lane & 3;
    const int m0 = blockIdx.y * 128, n0 = blockIdx.x * 128;

    uint32_t a_off[8], b_off[8];
#pragma unroll
    for (int l = 0; l < 2; l++) {
        int t = tid * 2 + l;
        int row = t >> 2, q4 = t & 3;
#pragma unroll
        for (int e = 0; e < 4; e++) {
            int k = q4 * 4 + e;
            int ks = k >> 3, kk = k & 7, ktt = kk & 3, kh = kk >> 2;
            int matom = row >> 4;
            int gi = row & 7, hi = (row >> 3) & 1;
            a_off[l * 4 + e] = (uint32_t)((((matom * 2 + ks) * 32 + gi * 4 + ktt) << 2) + hi + 2 * kh);
            int natom = row >> 3;
            int gb = row & 7;
            b_off[l * 4 + e] = (uint32_t)((((natom * 2 + ks) * 32 + gb * 4 + ktt) << 1) + kh);
        }
    }
    const int arow0 = (tid * 2) >> 2, aq0 = (tid * 2) & 3;
    const int arow1 = (tid * 2 + 1) >> 2, aq1 = (tid * 2 + 1) & 3;
    const float* Ap = A + (size_t)m0 * E_DIM;
    const float* Bp = Bt + (size_t)n0 * E_DIM;

    float d[4][4][4];
#pragma unroll
    for (int i = 0; i < 4; i++)
#pragma unroll
        for (int j = 0; j < 4; j++)
#pragma unroll
            for (int e = 0; e < 4; e++) d[i][j][e] = 0.f;

    float4 ra0, ra1, rb0, rb1;

#define LOADC(c) do { \
    ra0 = *(const float4*)(Ap + (size_t)arow0 * E_DIM + (c) * 16 + aq0 * 4); \
    ra1 = *(const float4*)(Ap + (size_t)arow1 * E_DIM + (c) * 16 + aq1 * 4); \
    rb0 = *(const float4*)(Bp + (size_t)arow0 * E_DIM + (c) * 16 + aq0 * 4); \
    rb1 = *(const float4*)(Bp + (size_t)arow1 * E_DIM + (c) * 16 + aq1 * 4); \
} while (0)

#define SCAT(bf_) do { \
    uint32_t* a_s = sA[bf_]; uint32_t* b_s = sB[bf_]; \
    a_s[a_off[0]] = tf32u(ra0.x); a_s[a_off[1]] = tf32u(ra0.y); \
    a_s[a_off[2]] = tf32u(ra0.z); a_s[a_off[3]] = tf32u(ra0.w); \
    a_s[a_off[4]] = tf32u(ra1.x); a_s[a_off[5]] = tf32u(ra1.y); \
    a_s[a_off[6]] = tf32u(ra1.z); a_s[a_off[7]] = tf32u(ra1.w); \
    b_s[b_off[0]] = __float_as_uint(rb0.x); b_s[b_off[1]] = __float_as_uint(rb0.y); \
    b_s[b_off[2]] = __float_as_uint(rb0.z); b_s[b_off[3]] = __float_as_uint(rb0.w); \
    b_s[b_off[4]] = __float_as_uint(rb1.x); b_s[b_off[5]] = __float_as_uint(rb1.y); \
    b_s[b_off[6]] = __float_as_uint(rb1.z); b_s[b_off[7]] = __float_as_uint(rb1.w); \
} while (0)

    LOADC(0);
    SCAT(0);
    __syncthreads();

    for (int c = 0; c < 64; c++) {
        const int buf = c & 1;
        if (c < 63) LOADC(c + 1);
#pragma unroll
        for (int ks = 0; ks < 2; ks++) {
            uint4 af[4];
            uint2 bfr[4];
#pragma unroll
            for (int ma = 0; ma < 4; ma++)
                af[ma] = *(const uint4*)&sA[buf][(((mw * 4 + ma) * 2 + ks) * 32 + lane) << 2];
#pragma unroll
            for (int nb = 0; nb < 4; nb++)
                bfr[nb] = *(const uint2*)&sB[buf][(((nw * 4 + nb) * 2 + ks) * 32 + lane) << 1];
#pragma unroll
            for (int ma = 0; ma < 4; ma++)
#pragma unroll
                for (int nb = 0; nb < 4; nb++)
                    MMA8(d[ma][nb], af[ma].x, af[ma].y, af[ma].z, af[ma].w,
                         bfr[nb].x, bfr[nb].y);
        }
        if (c < 63) SCAT(buf ^ 1);
        __syncthreads();
    }
#undef LOADC
#undef SCAT

#pragma unroll
    for (int ma = 0; ma < 4; ma++) {
        const int m_lo = m0 + mw * 64 + ma * 16 + g;
#pragma unroll
        for (int nb = 0; nb < 4; nb++) {
            const int n = n0 + nw * 32 + nb * 8 + tt * 2;
#pragma unroll
            for (int half = 0; half < 2; half++) {
                const int m = m_lo + half * 8;
                float2 v = make_float2(d[ma][nb][half * 2], d[ma][nb][half * 2 + 1]);
                if (mode == 0) {
                    int b = m >> 10, i = m & 1023, h = n >> 6, dd = n & 63;
                    *(float2*)&C[(((size_t)b * NH + h) * QLEN + i) * DH + dd] = v;
                } else if (mode == 1) {
                    int h = n >> 6, dd = n & 63;
                    *(float2*)&C[((size_t)h * QLEN + m) * DH + dd] = v;
                } else {
                    *(float2*)&C[(size_t)m * E_DIM + n] = v;
                }
            }
        }
    }
}

// ---------------- ck[b,h,j] = rwb[h].k ; cr[h,t] = rrb[h].rp ----------------
__global__ void __launch_bounds__(256) ckcr_kernel(const float* __restrict__ rwb,
                                                   const float* __restrict__ rrb)
{
    int gw = (blockIdx.x * blockDim.x + threadIdx.x) >> 5;
    int lane = threadIdx.x & 31;
    const int NCK = BATCH * NH * QLEN;  // 65536
    float s;
    if (gw < NCK) {
        int h = (gw >> 10) & (NH - 1);
        const float* row = g_k + (size_t)gw * DH;
        s = row[lane] * rwb[h * DH + lane] + row[lane + 32] * rwb[h * DH + lane + 32];
    } else {
        int w2 = gw - NCK;
        if (w2 >= NH * QLEN) return;
        int h = w2 >> 10;
        const float* row = g_rp + (size_t)w2 * DH;
        s = row[lane] * rrb[h * DH + lane] + row[lane + 32] * rrb[h * DH + lane + 32];
    }
#pragma unroll
    for (int off = 16; off; off >>= 1) s += __shfl_down_sync(0xffffffffu, s, off);
    if (lane == 0) {
        if (gw < NCK) g_ck[gw] = s;
        else g_cr[gw - NCK] = s;
    }
}

// ---------------- fused attention, tensor-core version ----------------
// grid (16 qtiles, 16 heads, 4 batch), 256 threads = 8 warps
// S[il,jl] = A'[il] . K'[jl]  +  A'[il] . RP'[u],  u = 63 - il + jl
//   A'  = [s*q, s, 0,0,0] (68 k-dims), K' = [k, ck, 0], RP' = [rp, cr, 0]
// P = A' @ RP'^T (64x128) scatters S (assign); S1 = A' @ K'^T accumulates.
// smem floats: q2 4352 | k 4352 | v 4608 | rp 8704 | S 4352 | m/l/c 192 = 26560
__global__ void __launch_bounds__(256, 2) attn_mma()
{
    extern __shared__ float sm[];
    float* q2_s = sm;                  // 64 x SA
    float* k_s  = sm + 4352;           // 64 x SA
    float* v_s  = sm + 8704;           // 64 x SV
    float* rp_s = sm + 13312;          // 128 x SA
    float* S_s  = sm + 22016;          // 64 x SS
    float* m_s  = sm + 26368;
    float* l_s  = sm + 26432;
    float* c_s  = sm + 26496;

    const int tid = threadIdx.x;
    const int wid = tid >> 5, lane = tid & 31;
    const int g = lane >> 2, tg = lane & 3;
    const int qt = 15 - blockIdx.x;    // heavy tiles first
    const int h = blockIdx.y, b = blockIdx.z;
    const int i0 = qt * 64;
    const size_t headbase = ((size_t)b * NH + h) * QLEN * DH;
    const size_t rpbase = (size_t)h * QLEN * DH;
    const size_t ckbase = ((size_t)b * NH + h) * QLEN;
    const int crbase = h * QLEN;

    const int mt = wid >> 1;           // m-tile (rows mt*16)
    const int nt = wid & 1;            // n-tile (S1/PV: cols nt*32; P: cols nt*64)

    // ---- q2 fill (once) ----
#pragma unroll
    for (int it = 0; it < 4; it++) {
        int idx4 = tid + 256 * it;
        int row = idx4 >> 4, c4 = (idx4 & 15) * 4;
        float4 qv = *(const float4*)(g_q + headbase + (size_t)(i0 + row) * DH + c4);
        q2_s[row * SA + c4 + 0] = tf32r(qv.x * 0.03125f);
        q2_s[row * SA + c4 + 1] = tf32r(qv.y * 0.03125f);
        q2_s[row * SA + c4 + 2] = tf32r(qv.z * 0.03125f);
        q2_s[row * SA + c4 + 3] = tf32r(qv.w * 0.03125f);
    }
    {
        int row = tid >> 2, cc = tid & 3;
        q2_s[row * SA + 64 + cc] = (cc == 0) ? 0.03125f : 0.f;
    }
    if (tid < 64) { m_s[tid] = -INFINITY; l_s[tid] = 0.f; }

    float acc_o[4][4];
#pragma unroll
    for (int na = 0; na < 4; na++)
#pragma unroll
        for (int e = 0; e < 4; e++) acc_o[na][e] = 0.f;

    const int arow0 = (mt * 16 + g) * SA;
    const int arow1 = arow0 + 8 * SA;
    __syncthreads();

    for (int kt = 0; kt <= qt; kt++) {
        const int j0 = kt * 64;
        const int m_base = 960 - i0 + j0;   // >= 0

        // ---- fills: k, v, rp (+ aux cols) ----
#pragma unroll
        for (int it = 0; it < 4; it++) {
            int idx4 = tid + 256 * it;
            int row = idx4 >> 4, c4 = (idx4 & 15) * 4;
            float4 kv = *(const float4*)(g_k + headbase + (size_t)(j0 + row) * DH + c4);
            k_s[row * SA + c4 + 0] = tf32r(kv.x);
            k_s[row * SA + c4 + 1] = tf32r(kv.y);
            k_s[row * SA + c4 + 2] = tf32r(kv.z);
            k_s[row * SA + c4 + 3] = tf32r(kv.w);
            float4 vv = *(const float4*)(g_v + headbase + (size_t)(j0 + row) * DH + c4);
            v_s[row * SV + c4 + 0] = tf32r(vv.x);
            v_s[row * SV + c4 + 1] = tf32r(vv.y);
            v_s[row * SV + c4 + 2] = tf32r(vv.z);
            v_s[row * SV + c4 + 3] = tf32r(vv.w);
        }
#pragma unroll
        for (int it = 0; it < 8; it++) {
            int idx4 = tid + 256 * it;
            int row = idx4 >> 4, c4 = (idx4 & 15) * 4;
            int mg = m_base + row;
            float4 rv = make_float4(0.f, 0.f, 0.f, 0.f);
            if (mg < QLEN) rv = *(const float4*)(g_rp + rpbase + (size_t)mg * DH + c4);
            rp_s[row * SA + c4 + 0] = tf32r(rv.x);
            rp_s[row * SA + c4 + 1] = tf32r(rv.y);
            rp_s[row * SA + c4 + 2] = tf32r(rv.z);
            rp_s[row * SA + c4 + 3] = tf32r(rv.w);
        }
        {
            int row = tid >> 2, cc = tid & 3;
            k_s[row * SA + 64 + cc] = (cc == 0) ? tf32r(g_ck[ckbase + j0 + row]) : 0.f;
        }
#pragma unroll
        for (int it = 0; it < 2; it++) {
            int idx = tid + 256 * it;
            int row = idx >> 2, cc = idx & 3;
            int mg = m_base + row;
            rp_s[row * SA + 64 + cc] = (cc == 0 && mg < QLEN) ? tf32r(g_cr[crbase + mg]) : 0.f;
        }
        __syncthreads();

        const uint32_t* q2u = (const uint32_t*)q2_s;
        const uint32_t* ku  = (const uint32_t*)k_s;
        const uint32_t* rpu = (const uint32_t*)rp_s;

        // ---- pass 1: S1 (4 atoms) + P-low (4 atoms), shared A frags ----
        float sc[4][4], pc[4][4];
#pragma unroll
        for (int na = 0; na < 4; na++)
#pragma unroll
            for (int e = 0; e < 4; e++) { sc[na][e] = 0.f; pc[na][e] = 0.f; }
#pragma unroll
        for (int ks = 0; ks < 8; ks++) {
            uint32_t a0 = q2u[arow0 + 8 * ks + tg];
            uint32_t a1 = q2u[arow1 + 8 * ks + tg];
            uint32_t a2 = q2u[arow0 + 8 * ks + 4 + tg];
            uint32_t a3 = q2u[arow1 + 8 * ks + 4 + tg];
#pragma unroll
            for (int na = 0; na < 4; na++) {
                int br = (nt * 32 + na * 8 + g) * SA + 8 * ks;
                MMA8(sc[na], a0, a1, a2, a3, ku[br + tg], ku[br + 4 + tg]);
            }
#pragma unroll
            for (int na = 0; na < 4; na++) {
                int br = (nt * 64 + na * 8 + g) * SA + 8 * ks;
                MMA8(pc[na], a0, a1, a2, a3, rpu[br + tg], rpu[br + 4 + tg]);
            }
        }
        {   // k4 tail (aux cols 64..67)
            uint32_t a0 = q2u[arow0 + 64 + tg];
            uint32_t a1 = q2u[arow1 + 64 + tg];
#pragma unroll
            for (int na = 0; na < 4; na++)
                MMA4(sc[na], a0, a1, ku[(nt * 32 + na * 8 + g) * SA + 64 + tg]);
#pragma unroll
            for (int na = 0; na < 4; na++)
                MMA4(pc[na], a0, a1, rpu[(nt * 64 + na * 8 + g) * SA + 64 + tg]);
        }
        // scatter P-low (assign into S band)
#pragma unroll
        for (int na = 0; na < 4; na++) {
            int ub = nt * 64 + na * 8 + 2 * tg;
#pragma unroll
            for (int e = 0; e < 4; e++) {
                int il = mt * 16 + g + (e >> 1) * 8;
                int jl = ub + (e & 1) - 63 + il;
                if (jl >= 0 && jl < 64) S_s[il * SS + jl] = pc[na][e];
            }
        }
        // ---- pass 2: P-high (4 atoms) ----
#pragma unroll
        for (int na = 0; na < 4; na++)
#pragma unroll
            for (int e = 0; e < 4; e++) pc[na][e] = 0.f;
#pragma unroll
        for (int ks = 0; ks < 8; ks++) {
            uint32_t a0 = q2u[arow0 + 8 * ks + tg];
            uint32_t a1 = q2u[arow1 + 8 * ks + tg];
            uint32_t a2 = q2u[arow0 + 8 * ks + 4 + tg];
            uint32_t a3 = q2u[arow1 + 8 * ks + 4 + tg];
#pragma unroll
            for (int na = 0; na < 4; na++) {
                int br = (nt * 64 + 32 + na * 8 + g) * SA + 8 * ks;
                MMA8(pc[na], a0, a1, a2, a3, rpu[br + tg], rpu[br + 4 + tg]);
            }
        }
        {
            uint32_t a0 = q2u[arow0 + 64 + tg];
            uint32_t a1 = q2u[arow1 + 64 + tg];
#pragma unroll
            for (int na = 0; na < 4; na++)
                MMA4(pc[na], a0, a1, rpu[(nt * 64 + 32 + na * 8 + g) * SA + 64 + tg]);
        }
#pragma unroll
        for (int na = 0; na < 4; na++) {
            int ub = nt * 64 + 32 + na * 8 + 2 * tg;
#pragma unroll
            for (int e = 0; e < 4; e++) {
                int il = mt * 16 + g + (e >> 1) * 8;
                int jl = ub + (e & 1) - 63 + il;
                if (jl >= 0 && jl < 64) S_s[il * SS + jl] = pc[na][e];
            }
        }
        __syncthreads();

        // ---- S1 accumulate into S ----
#pragma unroll
        for (int na = 0; na < 4; na++) {
            int cb = nt * 32 + na * 8 + 2 * tg;
            int il0 = mt * 16 + g;
            S_s[il0 * SS + cb]           += sc[na][0];
            S_s[il0 * SS + cb + 1]       += sc[na][1];
            S_s[(il0 + 8) * SS + cb]     += sc[na][2];
            S_s[(il0 + 8) * SS + cb + 1] += sc[na][3];
        }
        __syncthreads();

        // ---- online softmax: 4 threads per row ----
        {
            int row = tid >> 2, p = tid & 3;
            int c0 = p * 16;
            bool diag = (kt == qt);
            float mo = m_s[row];
            float mx = mo;
#pragma unroll
            for (int j = 0; j < 16; j++) {
                int jl = c0 + j;
                float v = S_s[row * SS + jl];
                if (diag && jl > row) v = -1e30f;
                mx = fmaxf(mx, v);
            }
            mx = fmaxf(mx, __shfl_xor_sync(0xffffffffu, mx, 1));
            mx = fmaxf(mx, __shfl_xor_sync(0xffffffffu, mx, 2));
            float corr = __expf(mo - mx);
            float sum = 0.f;
#pragma unroll
            for (int j = 0; j < 16; j++) {
                int jl = c0 + j;
                float v = S_s[row * SS + jl];
                if (diag && jl > row) v = -1e30f;
                float pe = __expf(v - mx);
                S_s[row * SS + jl] = tf32r(pe);
                sum += pe;
            }
            sum += __shfl_xor_sync(0xffffffffu, sum, 1);
            sum += __shfl_xor_sync(0xffffffffu, sum, 2);
            if (p == 0) {
                m_s[row] = mx;
                l_s[row] = l_s[row] * corr + sum;
                c_s[row] = corr;
            }
        }
        __syncthreads();

        // ---- PV: acc = acc*corr + Prob @ V ----
        {
            float cr0 = c_s[mt * 16 + g], cr1 = c_s[mt * 16 + 8 + g];
#pragma unroll
            for (int na = 0; na < 4; na++) {
                acc_o[na][0] *= cr0; acc_o[na][1] *= cr0;
                acc_o[na][2] *= cr1; acc_o[na][3] *= cr1;
            }
            const uint32_t* su = (const uint32_t*)S_s;
            const uint32_t* vu = (const uint32_t*)v_s;
            int sr0 = (mt * 16 + g) * SS, sr1 = sr0 + 8 * SS;
#pragma unroll
            for (int ks = 0; ks < 8; ks++) {
                uint32_t a0 = su[sr0 + 8 * ks + tg];
                uint32_t a1 = su[sr1 + 8 * ks + tg];
                uint32_t a2 = su[sr0 + 8 * ks + 4 + tg];
                uint32_t a3 = su[sr1 + 8 * ks + 4 + tg];
#pragma unroll
                for (int na = 0; na < 4; na++) {
                    int bc = nt * 32 + na * 8 + g;
                    uint32_t b0 = vu[(8 * ks + tg) * SV + bc];
                    uint32_t b1 = vu[(8 * ks + 4 + tg) * SV + bc];
                    MMA8(acc_o[na], a0, a1, a2, a3, b0, b1);
                }
            }
        }
        __syncthreads();
    }

    // ---- write out (token-major for Wo GEMM) ----
    {
        int il0 = mt * 16 + g;
        float inv0 = 1.f / l_s[il0], inv1 = 1.f / l_s[il0 + 8];
#pragma unroll
        for (int na = 0; na < 4; na++) {
            int d0 = h * DH + nt * 32 + na * 8 + 2 * tg;
            size_t o0 = ((size_t)b * QLEN + i0 + il0) * E_DIM + d0;
            size_t o1 = ((size_t)b * QLEN + i0 + il0 + 8) * E_DIM + d0;
            *(float2*)&g_attn[o0] = make_float2(acc_o[na][0] * inv0, acc_o[na][1] * inv0);
            *(float2*)&g_attn[o1] = make_float2(acc_o[na][2] * inv1, acc_o[na][3] * inv1);
        }
    }
}

// ---------------- residual + layernorm ----------------
__global__ void __launch_bounds__(256) addln_kernel(const float* __restrict__ w,
                                                    const float* __restrict__ gamma,
                                                    const float* __restrict__ beta,
                                                    float* __restrict__ out)
{
    __shared__ float xs[E_DIM];
    __shared__ float red[64];
    int row = blockIdx.x;
    size_t base = (size_t)row * E_DIM;
    float s = 0.f, s2 = 0.f;
    for (int j = threadIdx.x; j < E_DIM; j += 256) {
        float x = w[base + j] + g_o[base + j];
        xs[j] = x;
        s += x; s2 += x * x;
    }
#pragma unroll
    for (int off = 16; off; off >>= 1) {
        s  += __shfl_down_sync(0xffffffffu, s, off);
        s2 += __shfl_down_sync(0xffffffffu, s2, off);
    }
    int wid = threadIdx.x >> 5, lane = threadIdx.x & 31;
    if (lane == 0) { red[wid] = s; red[32 + wid] = s2; }
    __syncthreads();
    if (threadIdx.x == 0) {
        float S = 0.f, S2 = 0.f;
        for (int i = 0; i < 8; i++) { S += red[i]; S2 += red[32 + i]; }
        red[0] = S; red[1] = S2;
    }
    __syncthreads();
    float mean = red[0] * (1.f / E_DIM);
    float var = red[1] * (1.f / E_DIM) - mean * mean;
    float inv = rsqrtf(var + 1e-3f);
    for (int j = threadIdx.x; j < E_DIM; j += 256)
        out[base + j] = (xs[j] - mean) * inv * gamma[j] + beta[j];
}

// ---------------- launch ----------------
extern "C" void kernel_launch(void* const* d_in, const int* in_sizes, int n_in,
                              void* d_out, int out_size)
{
    const float* w     = (const float*)d_in[0];
    const float* r     = (const float*)d_in[1];
    const float* rwb   = (const float*)d_in[2];
    const float* rrb   = (const float*)d_in[3];
    // d_in[4] attn_mask: strictly-causal, computed analytically
    const float* Wq    = (const float*)d_in[5];
    const float* Wk    = (const float*)d_in[6];
    const float* Wv    = (const float*)d_in[7];
    const float* Wr    = (const float*)d_in[8];
    const float* Wo    = (const float*)d_in[9];
    const float* gamma = (const float*)d_in[10];
    const float* beta  = (const float*)d_in[11];
    float* out = (float*)d_out;

    const int ATTN_SMEM = 26560 * (int)sizeof(float);   // 106240 B
    cudaFuncSetAttribute(attn_mma, cudaFuncAttributeMaxDynamicSharedMemorySize, ATTN_SMEM);

    static float* p_wt = nullptr;
    static float* p_q = nullptr; static float* p_k = nullptr; static float* p_v = nullptr;
    static float* p_rp = nullptr; static float* p_attn = nullptr; static float* p_o = nullptr;
    if (!p_wt) {
        cudaGetSymbolAddress((void**)&p_wt, g_wt);
        cudaGetSymbolAddress((void**)&p_q, g_q);
        cudaGetSymbolAddress((void**)&p_k, g_k);
        cudaGetSymbolAddress((void**)&p_v, g_v);
        cudaGetSymbolAddress((void**)&p_rp, g_rp);
        cudaGetSymbolAddress((void**)&p_attn, g_attn);
        cudaGetSymbolAddress((void**)&p_o, g_o);
    }
    const size_t WSZ = (size_t)E_DIM * E_DIM;

    transpose5<<<dim3(32, 32, 5), dim3(32, 8)>>>(Wq, Wk, Wv, Wr, Wo);
    gemm_mma<<<dim3(8, 32), 256>>>(w, p_wt + 0 * WSZ, p_q, 0);
    gemm_mma<<<dim3(8, 32), 256>>>(w, p_wt + 1 * WSZ, p_k, 0);
    gemm_mma<<<dim3(8, 32), 256>>>(w, p_wt + 2 * WSZ, p_v, 0);
    gemm_mma<<<dim3(8, 8),  256>>>(r, p_wt + 3 * WSZ, p_rp, 1);
    ckcr_kernel<<<10240, 256>>>(rwb, rrb);
    attn_mma<<<dim3(16, 16, 4), 256, ATTN_SMEM>>>();
    gemm_mma<<<dim3(8, 32), 256>>>(p_attn, p_wt + 4 * WSZ, p_o, 2);
    addln_kernel<<<4096, 256>>>(w, gamma, beta, out);
}

// round 5
// speedup vs baseline: 3.2219x; 1.6123x over previous
#include <cuda_runtime.h>
#include <math.h>
#include <stdint.h>

#define E_DIM 1024
#define QLEN  1024
#define BATCH 4
#define NH    16
#define DH    64

// attention smem strides
#define SA 68   // q2/k/rp stride (64 data + 4 aux cols)
#define SV 72   // v stride
#define SS 68   // S stride

// ---------------- scratch (device globals; no allocation allowed) ----------------
__device__ float g_q[BATCH * NH * QLEN * DH];     // [b][h][i][d]
__device__ float g_k[BATCH * NH * QLEN * DH];
__device__ float g_v[BATCH * NH * QLEN * DH];
__device__ float g_rp[NH * QLEN * DH];            // [h][t][d]
__device__ float g_ck[BATCH * NH * QLEN];         // rwb . k
__device__ float g_cr[NH * QLEN];                 // rrb . rp
__device__ float g_attn[BATCH * QLEN * E_DIM];    // attention out, token-major
__device__ float g_o[BATCH * QLEN * E_DIM];       // after Wo
__device__ float g_wt[5 * E_DIM * E_DIM];         // transposed tf32-rounded weights

// ================= helpers =================
__device__ __forceinline__ float tf32r(float x) {
    asm("cvt.rna.tf32.f32 %0, %1;" : "=f"(x) : "f"(x));
    return x;
}
__device__ __forceinline__ uint32_t tf32u(float x) {
    uint32_t u;
    asm("cvt.rna.tf32.f32 %0, %1;" : "=r"(u) : "f"(x));
    return u;
}

#define MMA8(d, a0, a1, a2, a3, b0, b1) \
    asm volatile("mma.sync.aligned.m16n8k8.row.col.f32.tf32.tf32.f32 " \
        "{%0,%1,%2,%3}, {%4,%5,%6,%7}, {%8,%9}, {%0,%1,%2,%3};" \
        : "+f"((d)[0]), "+f"((d)[1]), "+f"((d)[2]), "+f"((d)[3]) \
        : "r"(a0), "r"(a1), "r"(a2), "r"(a3), "r"(b0), "r"(b1))

#define MMA4(d, a0, a1, b0) \
    asm volatile("mma.sync.aligned.m16n8k4.row.col.f32.tf32.tf32.f32 " \
        "{%0,%1,%2,%3}, {%4,%5}, {%6}, {%0,%1,%2,%3};" \
        : "+f"((d)[0]), "+f"((d)[1]), "+f"((d)[2]), "+f"((d)[3]) \
        : "r"(a0), "r"(a1), "r"(b0))

// ---------------- weight transpose + tf32 round: 5 x 1024x1024 ----------------
__global__ void __launch_bounds__(256) transpose5(const float* __restrict__ a0,
                                                  const float* __restrict__ a1,
                                                  const float* __restrict__ a2,
                                                  const float* __restrict__ a3,
                                                  const float* __restrict__ a4)
{
    __shared__ float t[32][33];
    const float* src = (blockIdx.z == 0) ? a0 : (blockIdx.z == 1) ? a1 :
                       (blockIdx.z == 2) ? a2 : (blockIdx.z == 3) ? a3 : a4;
    float* dst = g_wt + (size_t)blockIdx.z * E_DIM * E_DIM;
    int x = blockIdx.x * 32 + threadIdx.x;
    int y0 = blockIdx.y * 32 + threadIdx.y;
#pragma unroll
    for (int j = 0; j < 4; j++)
        t[threadIdx.y + 8 * j][threadIdx.x] = src[(size_t)(y0 + 8 * j) * E_DIM + x];
    __syncthreads();
    int x2 = blockIdx.y * 32 + threadIdx.x;
    int y2 = blockIdx.x * 32 + threadIdx.y;
#pragma unroll
    for (int j = 0; j < 4; j++)
        dst[(size_t)(y2 + 8 * j) * E_DIM + x2] = tf32r(t[threadIdx.x][threadIdx.y + 8 * j]);
}

// ---------------- mma.sync tf32 GEMM v2: C[MxN] = A[MxK] * Bt[NxK]^T, K=1024 ----------------
// 128 threads = 4 warps (2m x 2n), warp tile 64x64, block tile 128x128, k-chunk 16.
// smem: canonical row-major + XOR swizzle word = row*16 + (col ^ ((row&6)<<1));
// conflict-free STS.128 fills and LDS.32 fragment reads.
__global__ void __launch_bounds__(128, 2) gemm_mma(const float* __restrict__ A,
                                                   const float* __restrict__ Bt,
                                                   float* __restrict__ C,
                                                   int mode)
{
    __shared__ uint32_t sA[2][2048];
    __shared__ uint32_t sB[2][2048];

    const int tid = threadIdx.x;
    const int wid = tid >> 5, lane = tid & 31;
    const int mw = wid >> 1, nw = wid & 1;
    const int g = lane >> 2, tt = lane & 3;
    const int m0 = blockIdx.y * 128, n0 = blockIdx.x * 128;
    const int swz = (g & 6) << 1;
    const int c0w = tt + (0 ^ swz);      // col-part for kh=0 (XOR ks<<3 later)
    const int c1w = tt + (4 ^ swz);      // col-part for kh=1
    const int baseA = (mw * 64 + g) * 16;
    const int baseB = (nw * 64 + g) * 16;

    // fill mapping: q4 const per thread, rows row0 + 32*l
    const int q4 = tid & 3;
    const int row0 = tid >> 2;
    int f_w[4];
#pragma unroll
    for (int l = 0; l < 4; l++) {
        int row = row0 + 32 * l;
        f_w[l] = row * 16 + ((4 * q4) ^ ((row & 6) << 1));
    }

    const float* Ap = A + (size_t)m0 * E_DIM + q4 * 4;
    const float* Bp = Bt + (size_t)n0 * E_DIM + q4 * 4;

    float d[4][8][4];
#pragma unroll
    for (int i = 0; i < 4; i++)
#pragma unroll
        for (int j = 0; j < 8; j++)
#pragma unroll
            for (int e = 0; e < 4; e++) d[i][j][e] = 0.f;

    float4 ra[4], rb[4];

#define LOADC(c) do { \
    _Pragma("unroll") \
    for (int l = 0; l < 4; l++) { \
        ra[l] = *(const float4*)(Ap + (size_t)(row0 + 32 * l) * E_DIM + (c) * 16); \
        rb[l] = *(const float4*)(Bp + (size_t)(row0 + 32 * l) * E_DIM + (c) * 16); \
    } \
} while (0)

#define SCAT(bf_) do { \
    _Pragma("unroll") \
    for (int l = 0; l < 4; l++) { \
        uint4 va; \
        va.x = tf32u(ra[l].x); va.y = tf32u(ra[l].y); \
        va.z = tf32u(ra[l].z); va.w = tf32u(ra[l].w); \
        *(uint4*)&sA[bf_][f_w[l]] = va; \
        *(uint4*)&sB[bf_][f_w[l]] = *(const uint4*)&rb[l]; \
    } \
} while (0)

    LOADC(0);
    SCAT(0);
    __syncthreads();

    for (int c = 0; c < 64; c++) {
        const int buf = c & 1;
        if (c < 63) LOADC(c + 1);
#pragma unroll
        for (int ks = 0; ks < 2; ks++) {
            const int ko = ks << 3;
            uint32_t af[4][4];
            uint32_t bf2[8][2];
#pragma unroll
            for (int ma = 0; ma < 4; ma++) {
                af[ma][0] = sA[buf][baseA + ma * 256 +       (c0w ^ ko)];
                af[ma][1] = sA[buf][baseA + ma * 256 + 128 + (c0w ^ ko)];
                af[ma][2] = sA[buf][baseA + ma * 256 +       (c1w ^ ko)];
                af[ma][3] = sA[buf][baseA + ma * 256 + 128 + (c1w ^ ko)];
            }
#pragma unroll
            for (int nb = 0; nb < 8; nb++) {
                bf2[nb][0] = sB[buf][baseB + nb * 128 + (c0w ^ ko)];
                bf2[nb][1] = sB[buf][baseB + nb * 128 + (c1w ^ ko)];
            }
#pragma unroll
            for (int ma = 0; ma < 4; ma++)
#pragma unroll
                for (int nb = 0; nb < 8; nb++)
                    MMA8(d[ma][nb], af[ma][0], af[ma][1], af[ma][2], af[ma][3],
                         bf2[nb][0], bf2[nb][1]);
        }
        if (c < 63) SCAT(buf ^ 1);
        __syncthreads();
    }
#undef LOADC
#undef SCAT

    // epilogue: direct register -> gmem stores (float2 pairs)
#pragma unroll
    for (int ma = 0; ma < 4; ma++) {
        const int m_base = m0 + mw * 64 + ma * 16 + g;
#pragma unroll
        for (int nb = 0; nb < 8; nb++) {
            const int n = n0 + nw * 64 + nb * 8 + tt * 2;
#pragma unroll
            for (int half = 0; half < 2; half++) {
                const int m = m_base + half * 8;
                float2 v = make_float2(d[ma][nb][half * 2], d[ma][nb][half * 2 + 1]);
                if (mode == 0) {
                    int b = m >> 10, i = m & 1023, h = n >> 6, dd = n & 63;
                    *(float2*)&C[(((size_t)b * NH + h) * QLEN + i) * DH + dd] = v;
                } else if (mode == 1) {
                    int h = n >> 6, dd = n & 63;
                    *(float2*)&C[((size_t)h * QLEN + m) * DH + dd] = v;
                } else {
                    *(float2*)&C[(size_t)m * E_DIM + n] = v;
                }
            }
        }
    }
}

// ---------------- ck[b,h,j] = rwb[h].k ; cr[h,t] = rrb[h].rp ----------------
__global__ void __launch_bounds__(256) ckcr_kernel(const float* __restrict__ rwb,
                                                   const float* __restrict__ rrb)
{
    int gw = (blockIdx.x * blockDim.x + threadIdx.x) >> 5;
    int lane = threadIdx.x & 31;
    const int NCK = BATCH * NH * QLEN;  // 65536
    float s;
    if (gw < NCK) {
        int h = (gw >> 10) & (NH - 1);
        const float* row = g_k + (size_t)gw * DH;
        s = row[lane] * rwb[h * DH + lane] + row[lane + 32] * rwb[h * DH + lane + 32];
    } else {
        int w2 = gw - NCK;
        if (w2 >= NH * QLEN) return;
        int h = w2 >> 10;
        const float* row = g_rp + (size_t)w2 * DH;
        s = row[lane] * rrb[h * DH + lane] + row[lane + 32] * rrb[h * DH + lane + 32];
    }
#pragma unroll
    for (int off = 16; off; off >>= 1) s += __shfl_down_sync(0xffffffffu, s, off);
    if (lane == 0) {
        if (gw < NCK) g_ck[gw] = s;
        else g_cr[gw - NCK] = s;
    }
}

// ---------------- fused attention, tensor-core version ----------------
// grid (16 qtiles, 16 heads, 4 batch), 256 threads = 8 warps
__global__ void __launch_bounds__(256, 2) attn_mma()
{
    extern __shared__ float sm[];
    float* q2_s = sm;                  // 64 x SA
    float* k_s  = sm + 4352;           // 64 x SA
    float* v_s  = sm + 8704;           // 64 x SV
    float* rp_s = sm + 13312;          // 128 x SA
    float* S_s  = sm + 22016;          // 64 x SS
    float* m_s  = sm + 26368;
    float* l_s  = sm + 26432;
    float* c_s  = sm + 26496;

    const int tid = threadIdx.x;
    const int wid = tid >> 5, lane = tid & 31;
    const int g = lane >> 2, tg = lane & 3;
    const int qt = 15 - blockIdx.x;    // heavy tiles first
    const int h = blockIdx.y, b = blockIdx.z;
    const int i0 = qt * 64;
    const size_t headbase = ((size_t)b * NH + h) * QLEN * DH;
    const size_t rpbase = (size_t)h * QLEN * DH;
    const size_t ckbase = ((size_t)b * NH + h) * QLEN;
    const int crbase = h * QLEN;

    const int mt = wid >> 1;           // m-tile (rows mt*16)
    const int nt = wid & 1;            // n-tile

    // ---- q2 fill (once) ----
#pragma unroll
    for (int it = 0; it < 4; it++) {
        int idx4 = tid + 256 * it;
        int row = idx4 >> 4, c4 = (idx4 & 15) * 4;
        float4 qv = *(const float4*)(g_q + headbase + (size_t)(i0 + row) * DH + c4);
        q2_s[row * SA + c4 + 0] = tf32r(qv.x * 0.03125f);
        q2_s[row * SA + c4 + 1] = tf32r(qv.y * 0.03125f);
        q2_s[row * SA + c4 + 2] = tf32r(qv.z * 0.03125f);
        q2_s[row * SA + c4 + 3] = tf32r(qv.w * 0.03125f);
    }
    {
        int row = tid >> 2, cc = tid & 3;
        q2_s[row * SA + 64 + cc] = (cc == 0) ? 0.03125f : 0.f;
    }
    if (tid < 64) { m_s[tid] = -INFINITY; l_s[tid] = 0.f; }

    float acc_o[4][4];
#pragma unroll
    for (int na = 0; na < 4; na++)
#pragma unroll
        for (int e = 0; e < 4; e++) acc_o[na][e] = 0.f;

    const int arow0 = (mt * 16 + g) * SA;
    const int arow1 = arow0 + 8 * SA;
    __syncthreads();

    for (int kt = 0; kt <= qt; kt++) {
        const int j0 = kt * 64;
        const int m_base = 960 - i0 + j0;   // >= 0

        // ---- fills: k, v, rp (+ aux cols) ----
#pragma unroll
        for (int it = 0; it < 4; it++) {
            int idx4 = tid + 256 * it;
            int row = idx4 >> 4, c4 = (idx4 & 15) * 4;
            float4 kv = *(const float4*)(g_k + headbase + (size_t)(j0 + row) * DH + c4);
            k_s[row * SA + c4 + 0] = tf32r(kv.x);
            k_s[row * SA + c4 + 1] = tf32r(kv.y);
            k_s[row * SA + c4 + 2] = tf32r(kv.z);
            k_s[row * SA + c4 + 3] = tf32r(kv.w);
            float4 vv = *(const float4*)(g_v + headbase + (size_t)(j0 + row) * DH + c4);
            v_s[row * SV + c4 + 0] = tf32r(vv.x);
            v_s[row * SV + c4 + 1] = tf32r(vv.y);
            v_s[row * SV + c4 + 2] = tf32r(vv.z);
            v_s[row * SV + c4 + 3] = tf32r(vv.w);
        }
#pragma unroll
        for (int it = 0; it < 8; it++) {
            int idx4 = tid + 256 * it;
            int row = idx4 >> 4, c4 = (idx4 & 15) * 4;
            int mg = m_base + row;
            float4 rv = make_float4(0.f, 0.f, 0.f, 0.f);
            if (mg < QLEN) rv = *(const float4*)(g_rp + rpbase + (size_t)mg * DH + c4);
            rp_s[row * SA + c4 + 0] = tf32r(rv.x);
            rp_s[row * SA + c4 + 1] = tf32r(rv.y);
            rp_s[row * SA + c4 + 2] = tf32r(rv.z);
            rp_s[row * SA + c4 + 3] = tf32r(rv.w);
        }
        {
            int row = tid >> 2, cc = tid & 3;
            k_s[row * SA + 64 + cc] = (cc == 0) ? tf32r(g_ck[ckbase + j0 + row]) : 0.f;
        }
#pragma unroll
        for (int it = 0; it < 2; it++) {
            int idx = tid + 256 * it;
            int row = idx >> 2, cc = idx & 3;
            int mg = m_base + row;
            rp_s[row * SA + 64 + cc] = (cc == 0 && mg < QLEN) ? tf32r(g_cr[crbase + mg]) : 0.f;
        }
        __syncthreads();

        const uint32_t* q2u = (const uint32_t*)q2_s;
        const uint32_t* ku  = (const uint32_t*)k_s;
        const uint32_t* rpu = (const uint32_t*)rp_s;

        // ---- pass 1: S1 (4 atoms) + P-low (4 atoms), shared A frags ----
        float sc[4][4], pc[4][4];
#pragma unroll
        for (int na = 0; na < 4; na++)
#pragma unroll
            for (int e = 0; e < 4; e++) { sc[na][e] = 0.f; pc[na][e] = 0.f; }
#pragma unroll
        for (int ks = 0; ks < 8; ks++) {
            uint32_t a0 = q2u[arow0 + 8 * ks + tg];
            uint32_t a1 = q2u[arow1 + 8 * ks + tg];
            uint32_t a2 = q2u[arow0 + 8 * ks + 4 + tg];
            uint32_t a3 = q2u[arow1 + 8 * ks + 4 + tg];
#pragma unroll
            for (int na = 0; na < 4; na++) {
                int br = (nt * 32 + na * 8 + g) * SA + 8 * ks;
                MMA8(sc[na], a0, a1, a2, a3, ku[br + tg], ku[br + 4 + tg]);
            }
#pragma unroll
            for (int na = 0; na < 4; na++) {
                int br = (nt * 64 + na * 8 + g) * SA + 8 * ks;
                MMA8(pc[na], a0, a1, a2, a3, rpu[br + tg], rpu[br + 4 + tg]);
            }
        }
        {   // k4 tail (aux cols 64..67)
            uint32_t a0 = q2u[arow0 + 64 + tg];
            uint32_t a1 = q2u[arow1 + 64 + tg];
#pragma unroll
            for (int na = 0; na < 4; na++)
                MMA4(sc[na], a0, a1, ku[(nt * 32 + na * 8 + g) * SA + 64 + tg]);
#pragma unroll
            for (int na = 0; na < 4; na++)
                MMA4(pc[na], a0, a1, rpu[(nt * 64 + na * 8 + g) * SA + 64 + tg]);
        }
        // scatter P-low (assign into S band)
#pragma unroll
        for (int na = 0; na < 4; na++) {
            int ub = nt * 64 + na * 8 + 2 * tg;
#pragma unroll
            for (int e = 0; e < 4; e++) {
                int il = mt * 16 + g + (e >> 1) * 8;
                int jl = ub + (e & 1) - 63 + il;
                if (jl >= 0 && jl < 64) S_s[il * SS + jl] = pc[na][e];
            }
        }
        // ---- pass 2: P-high (4 atoms) ----
#pragma unroll
        for (int na = 0; na < 4; na++)
#pragma unroll
            for (int e = 0; e < 4; e++) pc[na][e] = 0.f;
#pragma unroll
        for (int ks = 0; ks < 8; ks++) {
            uint32_t a0 = q2u[arow0 + 8 * ks + tg];
            uint32_t a1 = q2u[arow1 + 8 * ks + tg];
            uint32_t a2 = q2u[arow0 + 8 * ks + 4 + tg];
            uint32_t a3 = q2u[arow1 + 8 * ks + 4 + tg];
#pragma unroll
            for (int na = 0; na < 4; na++) {
                int br = (nt * 64 + 32 + na * 8 + g) * SA + 8 * ks;
                MMA8(pc[na], a0, a1, a2, a3, rpu[br + tg], rpu[br + 4 + tg]);
            }
        }
        {
            uint32_t a0 = q2u[arow0 + 64 + tg];
            uint32_t a1 = q2u[arow1 + 64 + tg];
#pragma unroll
            for (int na = 0; na < 4; na++)
                MMA4(pc[na], a0, a1, rpu[(nt * 64 + 32 + na * 8 + g) * SA + 64 + tg]);
        }
#pragma unroll
        for (int na = 0; na < 4; na++) {
            int ub = nt * 64 + 32 + na * 8 + 2 * tg;
#pragma unroll
            for (int e = 0; e < 4; e++) {
                int il = mt * 16 + g + (e >> 1) * 8;
                int jl = ub + (e & 1) - 63 + il;
                if (jl >= 0 && jl < 64) S_s[il * SS + jl] = pc[na][e];
            }
        }
        __syncthreads();

        // ---- S1 accumulate into S ----
#pragma unroll
        for (int na = 0; na < 4; na++) {
            int cb = nt * 32 + na * 8 + 2 * tg;
            int il0 = mt * 16 + g;
            S_s[il0 * SS + cb]           += sc[na][0];
            S_s[il0 * SS + cb + 1]       += sc[na][1];
            S_s[(il0 + 8) * SS + cb]     += sc[na][2];
            S_s[(il0 + 8) * SS + cb + 1] += sc[na][3];
        }
        __syncthreads();

        // ---- online softmax: 4 threads per row ----
        {
            int row = tid >> 2, p = tid & 3;
            int c0 = p * 16;
            bool diag = (kt == qt);
            float mo = m_s[row];
            float mx = mo;
#pragma unroll
            for (int j = 0; j < 16; j++) {
                int jl = c0 + j;
                float v = S_s[row * SS + jl];
                if (diag && jl > row) v = -1e30f;
                mx = fmaxf(mx, v);
            }
            mx = fmaxf(mx, __shfl_xor_sync(0xffffffffu, mx, 1));
            mx = fmaxf(mx, __shfl_xor_sync(0xffffffffu, mx, 2));
            float corr = __expf(mo - mx);
            float sum = 0.f;
#pragma unroll
            for (int j = 0; j < 16; j++) {
                int jl = c0 + j;
                float v = S_s[row * SS + jl];
                if (diag && jl > row) v = -1e30f;
                float pe = __expf(v - mx);
                S_s[row * SS + jl] = tf32r(pe);
                sum += pe;
            }
            sum += __shfl_xor_sync(0xffffffffu, sum, 1);
            sum += __shfl_xor_sync(0xffffffffu, sum, 2);
            if (p == 0) {
                m_s[row] = mx;
                l_s[row] = l_s[row] * corr + sum;
                c_s[row] = corr;
            }
        }
        __syncthreads();

        // ---- PV: acc = acc*corr + Prob @ V ----
        {
            float cr0 = c_s[mt * 16 + g], cr1 = c_s[mt * 16 + 8 + g];
#pragma unroll
            for (int na = 0; na < 4; na++) {
                acc_o[na][0] *= cr0; acc_o[na][1] *= cr0;
                acc_o[na][2] *= cr1; acc_o[na][3] *= cr1;
            }
            const uint32_t* su = (const uint32_t*)S_s;
            const uint32_t* vu = (const uint32_t*)v_s;
            int sr0 = (mt * 16 + g) * SS, sr1 = sr0 + 8 * SS;
#pragma unroll
            for (int ks = 0; ks < 8; ks++) {
                uint32_t a0 = su[sr0 + 8 * ks + tg];
                uint32_t a1 = su[sr1 + 8 * ks + tg];
                uint32_t a2 = su[sr0 + 8 * ks + 4 + tg];
                uint32_t a3 = su[sr1 + 8 * ks + 4 + tg];
#pragma unroll
                for (int na = 0; na < 4; na++) {
                    int bc = nt * 32 + na * 8 + g;
                    uint32_t b0 = vu[(8 * ks + tg) * SV + bc];
                    uint32_t b1 = vu[(8 * ks + 4 + tg) * SV + bc];
                    MMA8(acc_o[na], a0, a1, a2, a3, b0, b1);
                }
            }
        }
        __syncthreads();
    }

    // ---- write out (token-major for Wo GEMM) ----
    {
        int il0 = mt * 16 + g;
        float inv0 = 1.f / l_s[il0], inv1 = 1.f / l_s[il0 + 8];
#pragma unroll
        for (int na = 0; na < 4; na++) {
            int d0 = h * DH + nt * 32 + na * 8 + 2 * tg;
            size_t o0 = ((size_t)b * QLEN + i0 + il0) * E_DIM + d0;
            size_t o1 = ((size_t)b * QLEN + i0 + il0 + 8) * E_DIM + d0;
            *(float2*)&g_attn[o0] = make_float2(acc_o[na][0] * inv0, acc_o[na][1] * inv0);
            *(float2*)&g_attn[o1] = make_float2(acc_o[na][2] * inv1, acc_o[na][3] * inv1);
        }
    }
}

// ---------------- residual + layernorm ----------------
__global__ void __launch_bounds__(256) addln_kernel(const float* __restrict__ w,
                                                    const float* __restrict__ gamma,
                                                    const float* __restrict__ beta,
                                                    float* __restrict__ out)
{
    __shared__ float xs[E_DIM];
    __shared__ float red[64];
    int row = blockIdx.x;
    size_t base = (size_t)row * E_DIM;
    float s = 0.f, s2 = 0.f;
    for (int j = threadIdx.x; j < E_DIM; j += 256) {
        float x = w[base + j] + g_o[base + j];
        xs[j] = x;
        s += x; s2 += x * x;
    }
#pragma unroll
    for (int off = 16; off; off >>= 1) {
        s  += __shfl_down_sync(0xffffffffu, s, off);
        s2 += __shfl_down_sync(0xffffffffu, s2, off);
    }
    int wid = threadIdx.x >> 5, lane = threadIdx.x & 31;
    if (lane == 0) { red[wid] = s; red[32 + wid] = s2; }
    __syncthreads();
    if (threadIdx.x == 0) {
        float S = 0.f, S2 = 0.f;
        for (int i = 0; i < 8; i++) { S += red[i]; S2 += red[32 + i]; }
        red[0] = S; red[1] = S2;
    }
    __syncthreads();
    float mean = red[0] * (1.f / E_DIM);
    float var = red[1] * (1.f / E_DIM) - mean * mean;
    float inv = rsqrtf(var + 1e-3f);
    for (int j = threadIdx.x; j < E_DIM; j += 256)
        out[base + j] = (xs[j] - mean) * inv * gamma[j] + beta[j];
}

// ---------------- launch ----------------
extern "C" void kernel_launch(void* const* d_in, const int* in_sizes, int n_in,
                              void* d_out, int out_size)
{
    const float* w     = (const float*)d_in[0];
    const float* r     = (const float*)d_in[1];
    const float* rwb   = (const float*)d_in[2];
    const float* rrb   = (const float*)d_in[3];
    // d_in[4] attn_mask: strictly-causal, computed analytically
    const float* Wq    = (const float*)d_in[5];
    const float* Wk    = (const float*)d_in[6];
    const float* Wv    = (const float*)d_in[7];
    const float* Wr    = (const float*)d_in[8];
    const float* Wo    = (const float*)d_in[9];
    const float* gamma = (const float*)d_in[10];
    const float* beta  = (const float*)d_in[11];
    float* out = (float*)d_out;

    const int ATTN_SMEM = 26560 * (int)sizeof(float);   // 106240 B
    cudaFuncSetAttribute(attn_mma, cudaFuncAttributeMaxDynamicSharedMemorySize, ATTN_SMEM);

    static float* p_wt = nullptr;
    static float* p_q = nullptr; static float* p_k = nullptr; static float* p_v = nullptr;
    static float* p_rp = nullptr; static float* p_attn = nullptr; static float* p_o = nullptr;
    if (!p_wt) {
        cudaGetSymbolAddress((void**)&p_wt, g_wt);
        cudaGetSymbolAddress((void**)&p_q, g_q);
        cudaGetSymbolAddress((void**)&p_k, g_k);
        cudaGetSymbolAddress((void**)&p_v, g_v);
        cudaGetSymbolAddress((void**)&p_rp, g_rp);
        cudaGetSymbolAddress((void**)&p_attn, g_attn);
        cudaGetSymbolAddress((void**)&p_o, g_o);
    }
    const size_t WSZ = (size_t)E_DIM * E_DIM;

    transpose5<<<dim3(32, 32, 5), dim3(32, 8)>>>(Wq, Wk, Wv, Wr, Wo);
    gemm_mma<<<dim3(8, 32), 128>>>(w, p_wt + 0 * WSZ, p_q, 0);
    gemm_mma<<<dim3(8, 32), 128>>>(w, p_wt + 1 * WSZ, p_k, 0);
    gemm_mma<<<dim3(8, 32), 128>>>(w, p_wt + 2 * WSZ, p_v, 0);
    gemm_mma<<<dim3(8, 8),  128>>>(r, p_wt + 3 * WSZ, p_rp, 1);
    ckcr_kernel<<<10240, 256>>>(rwb, rrb);
    attn_mma<<<dim3(16, 16, 4), 256, ATTN_SMEM>>>();
    gemm_mma<<<dim3(8, 32), 128>>>(p_attn, p_wt + 4 * WSZ, p_o, 2);
    addln_kernel<<<4096, 256>>>(w, gamma, beta, out);
}